// round 12
// baseline (speedup 1.0000x reference)
#include <cuda_runtime.h>
#include <cuda_fp16.h>

// ---- problem constants (hardcoded in reference module) ----
#define NN 57254
#define EE 916064
#define NPAD 57344           // 1024*56, padded counter array
#define BT 32768             // B*T

// ---- device scratch (static: no allocation allowed) ----
__device__ float  g_h1[NN * 128];     // layer-1 residual input (fp32)
__device__ float  g_hf[NN * 128];     // final normalized features
__device__ __half g_h0h[NN * 128];    // fp16 GEMM input, layer 0 (emb gathered)
__device__ __half g_h1h[NN * 128];    // fp16 GEMM input, layer 1
__device__ __half g_Wh0[128 * 128];
__device__ __half g_Wh1[128 * 128];
__device__ __half g_z [NN * 128];
__device__ float  g_el[NN * 8];
__device__ float  g_er[NN * 8];
__device__ int    g_rowptr[NN + 1];
__device__ int    g_cnt[NPAD];
__device__ int    g_csrc[EE];

// ---------------------------------------------------------------------------
// CSR build: count (int4), single-block 2-pass scan (also seeds g_cnt with
// the exclusive prefix so scatter needs no second memset), scatter
// ---------------------------------------------------------------------------
__global__ void k_count(const int4* __restrict__ dst4) {
    int i = blockIdx.x * blockDim.x + threadIdx.x;
    if (i < EE / 4) {
        int4 d = dst4[i];
        atomicAdd(&g_cnt[d.x], 1);
        atomicAdd(&g_cnt[d.y], 1);
        atomicAdd(&g_cnt[d.z], 1);
        atomicAdd(&g_cnt[d.w], 1);
    }
}

__global__ __launch_bounds__(1024) void k_scan() {
    __shared__ int wsum[32];
    int t = threadIdx.x;
    int lane = t & 31, wid = t >> 5;
    const int4* c4 = (const int4*)g_cnt;

    int tot = 0;
    int4 vv[14];
    #pragma unroll
    for (int j = 0; j < 14; j++) {
        vv[j] = c4[t * 14 + j];
        tot += vv[j].x + vv[j].y + vv[j].z + vv[j].w;
    }
    int s = tot;
    #pragma unroll
    for (int o = 1; o < 32; o <<= 1) {
        int u = __shfl_up_sync(0xffffffffu, s, o);
        if (lane >= o) s += u;
    }
    if (lane == 31) wsum[wid] = s;
    __syncthreads();
    if (wid == 0) {
        int wv = wsum[lane];
        #pragma unroll
        for (int o = 1; o < 32; o <<= 1) {
            int u = __shfl_up_sync(0xffffffffu, wv, o);
            if (lane >= o) wv += u;
        }
        wsum[lane] = wv;
    }
    __syncthreads();
    int run = s - tot + (wid > 0 ? wsum[wid - 1] : 0);

    #pragma unroll
    for (int j = 0; j < 14; j++) {
        int4 v = vv[j];
        int idx = t * 56 + j * 4;
        if (idx + 3 < NN) {
            int4 o;
            o.x = run;             o.y = run + v.x;
            o.z = run + v.x + v.y; o.w = run + v.x + v.y + v.z;
            *(int4*)(g_rowptr + idx) = o;
            *(int4*)(g_cnt + idx) = o;          // scatter works in-place on cnt
            run += v.x + v.y + v.z + v.w;
        } else {
            if (idx     < NN) { g_rowptr[idx]     = run; g_cnt[idx]     = run; } run += v.x;
            if (idx + 1 < NN) { g_rowptr[idx + 1] = run; g_cnt[idx + 1] = run; } run += v.y;
            if (idx + 2 < NN) { g_rowptr[idx + 2] = run; g_cnt[idx + 2] = run; } run += v.z;
            if (idx + 3 < NN) { g_rowptr[idx + 3] = run; g_cnt[idx + 3] = run; } run += v.w;
        }
    }
    if (t == 1023) g_rowptr[NN] = EE;
}

__global__ void k_scatter(const int* __restrict__ src, const int* __restrict__ dst) {
    int i = blockIdx.x * blockDim.x + threadIdx.x;
    if (i >= EE) return;
    int pos = atomicAdd(&g_cnt[dst[i]], 1);
    g_csrc[pos] = src[i];
}

// ---------------------------------------------------------------------------
// fp16 input prep: emb[nf[n]] -> half h0; first 4096 threads also convert W0/W1
// ---------------------------------------------------------------------------
__global__ void k_gather_h(const float4* __restrict__ emb,
                           const int* __restrict__ nf,
                           const float4* __restrict__ W0,
                           const float4* __restrict__ W1) {
    int i = blockIdx.x * blockDim.x + threadIdx.x;   // NN*32 float4 slots
    if (i < 4096) {                                  // 128*128 floats = 4096 float4
        float4 w0 = W0[i], w1 = W1[i];
        __half2 a0 = __floats2half2_rn(w0.x, w0.y), b0 = __floats2half2_rn(w0.z, w0.w);
        __half2 a1 = __floats2half2_rn(w1.x, w1.y), b1 = __floats2half2_rn(w1.z, w1.w);
        uint2 u0, u1;
        u0.x = *(unsigned*)&a0; u0.y = *(unsigned*)&b0;
        u1.x = *(unsigned*)&a1; u1.y = *(unsigned*)&b1;
        *(uint2*)(g_Wh0 + i * 4) = u0;
        *(uint2*)(g_Wh1 + i * 4) = u1;
    }
    if (i >= NN * 32) return;
    int n = i >> 5, l = i & 31;
    float4 v = emb[(long)nf[n] * 32 + l];
    __half2 lo = __floats2half2_rn(v.x, v.y);
    __half2 hi = __floats2half2_rn(v.z, v.w);
    uint2 u;
    u.x = *(unsigned*)&lo;
    u.y = *(unsigned*)&hi;
    *(uint2*)(g_h0h + (long)n * 128 + l * 4) = u;
}

// ---------------------------------------------------------------------------
// fp16 tensor-core GEMM with fused scores:
//   z(fp16) = h @ W;  el = z . al;  er = z . ar
// 64x128 block tile, 256 threads (8 warps 2x4), warp tile 32x32
// (m16n8k16). Full tiles staged once via cp.async; ldmatrix feeds mma.
// ---------------------------------------------------------------------------
__device__ __forceinline__ void mma16(float* c, const unsigned* a,
                                      unsigned b0, unsigned b1) {
    asm volatile(
        "mma.sync.aligned.m16n8k16.row.col.f32.f16.f16.f32 "
        "{%0,%1,%2,%3},{%4,%5,%6,%7},{%8,%9},{%0,%1,%2,%3};"
        : "+f"(c[0]), "+f"(c[1]), "+f"(c[2]), "+f"(c[3])
        : "r"(a[0]), "r"(a[1]), "r"(a[2]), "r"(a[3]), "r"(b0), "r"(b1));
}

__device__ __forceinline__ void ldmx4(unsigned* r, unsigned addr) {
    asm volatile("ldmatrix.sync.aligned.m8n8.x4.shared.b16 {%0,%1,%2,%3}, [%4];"
                 : "=r"(r[0]), "=r"(r[1]), "=r"(r[2]), "=r"(r[3]) : "r"(addr));
}

__device__ __forceinline__ void ldmx4t(unsigned* r, unsigned addr) {
    asm volatile("ldmatrix.sync.aligned.m8n8.x4.trans.shared.b16 {%0,%1,%2,%3}, [%4];"
                 : "=r"(r[0]), "=r"(r[1]), "=r"(r[2]), "=r"(r[3]) : "r"(addr));
}

__device__ __forceinline__ void cpasync16(void* smem, const void* gmem, int bytes) {
    unsigned s = (unsigned)__cvta_generic_to_shared(smem);
    asm volatile("cp.async.cg.shared.global [%0], [%1], 16, %2;"
                 :: "r"(s), "l"(gmem), "r"(bytes));
}
#define CP_COMMIT() asm volatile("cp.async.commit_group;")

#define HST 136                          // halves per smem row (272 B)
#define GEMM_SMEM ((64 * HST + 128 * HST) * 2)

__global__ __launch_bounds__(256, 3) void k_gemm(const __half* __restrict__ Ah,
                                                 const __half* __restrict__ Wh,
                                                 const float* __restrict__ al,
                                                 const float* __restrict__ ar,
                                                 __half* __restrict__ z,
                                                 float* __restrict__ el,
                                                 float* __restrict__ er) {
    extern __shared__ __half smh[];
    __half* sA = smh;               // 64 x HST
    __half* sB = smh + 64 * HST;    // 128 x HST (W, k-major)

    int t = threadIdx.x;
    int rowbase = blockIdx.x * 64;
    int warp = t >> 5, lane = t & 31;
    int qr = lane >> 2, qc = lane & 3;
    int wm = (warp >> 2) * 32;
    int wn = (warp & 3) * 32;

    // ---- stage full A (64x128) and B (128x128) tiles ----
    #pragma unroll
    for (int j = 0; j < 4; j++) {
        int idx = t + j * 256;          // 0..1023
        int row = idx >> 4, seg = idx & 15;
        int gr = rowbase + row;
        const void* ga = (gr < NN) ? (const void*)(Ah + (long)gr * 128 + seg * 8)
                                   : (const void*)Ah;
        cpasync16(sA + row * HST + seg * 8, ga, gr < NN ? 16 : 0);
    }
    #pragma unroll
    for (int j = 0; j < 8; j++) {
        int idx = t + j * 256;          // 0..2047
        int row = idx >> 4, seg = idx & 15;
        cpasync16(sB + row * HST + seg * 8, Wh + (long)row * 128 + seg * 8, 16);
    }
    CP_COMMIT();

    float c[2][4][4];
    #pragma unroll
    for (int mt = 0; mt < 2; mt++)
        #pragma unroll
        for (int nt = 0; nt < 4; nt++)
            #pragma unroll
            for (int i = 0; i < 4; i++) c[mt][nt][i] = 0.f;

    unsigned sAsh = (unsigned)__cvta_generic_to_shared(sA);
    unsigned sBsh = (unsigned)__cvta_generic_to_shared(sB);
    int l8  = lane & 7;
    int m01 = (lane >> 3) & 1;
    int hi  = lane >> 4;
    unsigned aAddr0 = sAsh + ((wm + m01 * 8 + l8) * HST + hi * 8) * 2;
    unsigned aAddr1 = aAddr0 + 16 * HST * 2;
    unsigned bAddr0 = sBsh + ((m01 * 8 + l8) * HST + wn + hi * 8) * 2;
    unsigned bAddr1 = bAddr0 + 16 * 2;

    asm volatile("cp.async.wait_group 0;");
    __syncthreads();

    #pragma unroll
    for (int ks = 0; ks < 8; ks++) {
        unsigned a0[4], a1[4], b0[4], b1[4];
        ldmx4 (a0, aAddr0 + ks * 32);
        ldmx4 (a1, aAddr1 + ks * 32);
        ldmx4t(b0, bAddr0 + ks * 16 * HST * 2);
        ldmx4t(b1, bAddr1 + ks * 16 * HST * 2);
        mma16(c[0][0], a0, b0[0], b0[1]);
        mma16(c[1][0], a1, b0[0], b0[1]);
        mma16(c[0][1], a0, b0[2], b0[3]);
        mma16(c[1][1], a1, b0[2], b0[3]);
        mma16(c[0][2], a0, b1[0], b1[1]);
        mma16(c[1][2], a1, b1[0], b1[1]);
        mma16(c[0][3], a0, b1[2], b1[3]);
        mma16(c[1][3], a1, b1[2], b1[3]);
    }

    // ---- epilogue 1: store z as fp16 ----
    #pragma unroll
    for (int mt = 0; mt < 2; mt++) {
        int r0 = rowbase + wm + mt * 16 + qr;
        int r1 = r0 + 8;
        #pragma unroll
        for (int nt = 0; nt < 4; nt++) {
            int col = wn + nt * 8 + qc * 2;
            if (r0 < NN)
                *(__half2*)(z + (long)r0 * 128 + col) = __floats2half2_rn(c[mt][nt][0], c[mt][nt][1]);
            if (r1 < NN)
                *(__half2*)(z + (long)r1 * 128 + col) = __floats2half2_rn(c[mt][nt][2], c[mt][nt][3]);
        }
    }

    // ---- epilogue 2: fused el/er scores ----
    float alv[8], arv[8];
    #pragma unroll
    for (int nt = 0; nt < 4; nt++) {
        #pragma unroll
        for (int u = 0; u < 2; u++) {
            int col = wn + nt * 8 + qc * 2 + u;
            alv[nt * 2 + u] = __ldg(al + col);
            arv[nt * 2 + u] = __ldg(ar + col);
        }
    }
    #pragma unroll
    for (int mt = 0; mt < 2; mt++) {
        #pragma unroll
        for (int rh = 0; rh < 2; rh++) {
            #pragma unroll
            for (int hl = 0; hl < 2; hl++) {
                float pl = 0.f, pr = 0.f;
                #pragma unroll
                for (int k = 0; k < 2; k++) {
                    int nt = hl * 2 + k;
                    pl += c[mt][nt][rh * 2]     * alv[nt * 2]
                        + c[mt][nt][rh * 2 + 1] * alv[nt * 2 + 1];
                    pr += c[mt][nt][rh * 2]     * arv[nt * 2]
                        + c[mt][nt][rh * 2 + 1] * arv[nt * 2 + 1];
                }
                pl += __shfl_xor_sync(0xffffffffu, pl, 1);
                pl += __shfl_xor_sync(0xffffffffu, pl, 2);
                pr += __shfl_xor_sync(0xffffffffu, pr, 1);
                pr += __shfl_xor_sync(0xffffffffu, pr, 2);
                if ((lane & 3) == 0) {
                    int row = rowbase + wm + mt * 16 + qr + rh * 8;
                    if (row < NN) {
                        int hidx = (wn >> 4) + hl;
                        el[row * 8 + hidx] = pl;
                        er[row * 8 + hidx] = pr;
                    }
                }
            }
        }
    }
}

// ---------------------------------------------------------------------------
// Per-dst edge softmax + aggregate + residual + bias (+ leaky_relu / L2 norm).
// One warp/node, 8-edge deep load pipeline (MLP 8); residual/bias/er hoisted
// ahead of the edge loop.
// ---------------------------------------------------------------------------
__global__ __launch_bounds__(256) void k_aggregate(const uint2* __restrict__ zh,
                                                   const float* __restrict__ el,
                                                   const float* __restrict__ er,
                                                   const float* __restrict__ hin,
                                                   const int* __restrict__ nfmap,
                                                   const float* __restrict__ bias,
                                                   float* __restrict__ hout,
                                                   __half* __restrict__ houth,
                                                   int activate, int normalize) {
    int warp = (blockIdx.x * blockDim.x + threadIdx.x) >> 5;
    int lane = threadIdx.x & 31;
    if (warp >= NN) return;
    int hd = lane >> 2;

    // hoist tail operands so their latency hides under the edge loop
    int hidx = nfmap ? __ldg(nfmap + warp) : warp;
    float4 hv = __ldg((const float4*)hin + (long)hidx * 32 + lane);
    float4 bv = __ldg((const float4*)bias + lane);
    float erh = __ldg(er + warp * 8 + hd);

    int beg = g_rowptr[warp], end = g_rowptr[warp + 1];
    float s = 0.f;
    float4 acc = make_float4(0.f, 0.f, 0.f, 0.f);

    int e = beg;
    for (; e + 8 <= end; e += 8) {
        int si[8];
        #pragma unroll
        for (int k = 0; k < 8; k++) si[k] = __ldg(g_csrc + e + k);
        float xe[8];
        #pragma unroll
        for (int k = 0; k < 8; k++) xe[k] = __ldg(el + si[k] * 8 + hd);
        uint2 q[8];
        #pragma unroll
        for (int k = 0; k < 8; k++) q[k] = __ldg(zh + (long)si[k] * 32 + lane);
        #pragma unroll
        for (int k = 0; k < 8; k++) {
            float x = xe[k] + erh;
            x = x > 0.f ? x : 0.2f * x;
            float a = __expf(x);
            s += a;
            float2 p = __half22float2(*(__half2*)&q[k].x);
            float2 r = __half22float2(*(__half2*)&q[k].y);
            acc.x += a * p.x; acc.y += a * p.y;
            acc.z += a * r.x; acc.w += a * r.y;
        }
    }
    for (; e + 4 <= end; e += 4) {
        int si[4];
        #pragma unroll
        for (int k = 0; k < 4; k++) si[k] = __ldg(g_csrc + e + k);
        float xe[4];
        #pragma unroll
        for (int k = 0; k < 4; k++) xe[k] = __ldg(el + si[k] * 8 + hd);
        uint2 q[4];
        #pragma unroll
        for (int k = 0; k < 4; k++) q[k] = __ldg(zh + (long)si[k] * 32 + lane);
        #pragma unroll
        for (int k = 0; k < 4; k++) {
            float x = xe[k] + erh;
            x = x > 0.f ? x : 0.2f * x;
            float a = __expf(x);
            s += a;
            float2 p = __half22float2(*(__half2*)&q[k].x);
            float2 r = __half22float2(*(__half2*)&q[k].y);
            acc.x += a * p.x; acc.y += a * p.y;
            acc.z += a * r.x; acc.w += a * r.y;
        }
    }
    for (; e < end; e++) {
        int sr = __ldg(g_csrc + e);
        float x = __ldg(el + sr * 8 + hd) + erh;
        x = x > 0.f ? x : 0.2f * x;
        float a = __expf(x);
        uint2 qa = __ldg(zh + (long)sr * 32 + lane);
        float2 p = __half22float2(*(__half2*)&qa.x);
        float2 r = __half22float2(*(__half2*)&qa.y);
        s += a;
        acc.x += a * p.x; acc.y += a * p.y; acc.z += a * r.x; acc.w += a * r.y;
    }

    float inv = (s > 0.f) ? (1.f / s) : 0.f;
    float4 o;
    o.x = acc.x * inv + hv.x + bv.x;
    o.y = acc.y * inv + hv.y + bv.y;
    o.z = acc.z * inv + hv.z + bv.z;
    o.w = acc.w * inv + hv.w + bv.w;
    if (activate) {
        o.x = o.x > 0.f ? o.x : 0.01f * o.x;
        o.y = o.y > 0.f ? o.y : 0.01f * o.y;
        o.z = o.z > 0.f ? o.z : 0.01f * o.z;
        o.w = o.w > 0.f ? o.w : 0.01f * o.w;
    }
    if (normalize) {
        float ss = o.x * o.x + o.y * o.y + o.z * o.z + o.w * o.w;
        #pragma unroll
        for (int off = 16; off; off >>= 1)
            ss += __shfl_xor_sync(0xffffffffu, ss, off);
        float inv2 = 1.f / fmaxf(sqrtf(ss), 1e-5f);
        o.x *= inv2; o.y *= inv2; o.z *= inv2; o.w *= inv2;
    }
    ((float4*)hout)[warp * 32 + lane] = o;
    if (houth) {
        __half2 lo = __floats2half2_rn(o.x, o.y);
        __half2 hi = __floats2half2_rn(o.z, o.w);
        uint2 u;
        u.x = *(unsigned*)&lo;
        u.y = *(unsigned*)&hi;
        *(uint2*)(houth + (long)warp * 128 + lane * 4) = u;
    }
}

// ---------------------------------------------------------------------------
// out[i] = h[x[i]]  (pure gather; normalization already fused)
// ---------------------------------------------------------------------------
__global__ void k_output(const float4* __restrict__ h,
                         const int* __restrict__ x,
                         float4* __restrict__ out) {
    int i = blockIdx.x * blockDim.x + threadIdx.x;
    if (i >= BT * 32) return;
    int t = i >> 5, l = i & 31;
    out[i] = h[(long)x[t] * 32 + l];
}

// ---------------------------------------------------------------------------
// host launch: CSR build forked onto a side stream, overlapping prep + GEMM-0
// ---------------------------------------------------------------------------
extern "C" void kernel_launch(void* const* d_in, const int* in_sizes, int n_in,
                              void* d_out, int out_size) {
    const float* emb = (const float*)d_in[0];
    const float* W0  = (const float*)d_in[1];
    const float* al0 = (const float*)d_in[2];
    const float* ar0 = (const float*)d_in[3];
    const float* b0  = (const float*)d_in[4];
    const float* W1  = (const float*)d_in[5];
    const float* al1 = (const float*)d_in[6];
    const float* ar1 = (const float*)d_in[7];
    const float* b1  = (const float*)d_in[8];
    const int*   nf  = (const int*)d_in[9];
    const int*   src = (const int*)d_in[10];
    const int*   dst = (const int*)d_in[11];
    const int*   x   = (const int*)d_in[12];
    float* out = (float*)d_out;

    float *h1, *hf, *el, *er;
    __half *z, *h0h, *h1h, *Wh0, *Wh1;
    int *cnt;
    cudaGetSymbolAddress((void**)&h1,  g_h1);
    cudaGetSymbolAddress((void**)&hf,  g_hf);
    cudaGetSymbolAddress((void**)&z,   g_z);
    cudaGetSymbolAddress((void**)&h0h, g_h0h);
    cudaGetSymbolAddress((void**)&h1h, g_h1h);
    cudaGetSymbolAddress((void**)&Wh0, g_Wh0);
    cudaGetSymbolAddress((void**)&Wh1, g_Wh1);
    cudaGetSymbolAddress((void**)&el,  g_el);
    cudaGetSymbolAddress((void**)&er,  g_er);
    cudaGetSymbolAddress((void**)&cnt, g_cnt);

    cudaFuncSetAttribute(k_gemm, cudaFuncAttributeMaxDynamicSharedMemorySize, GEMM_SMEM);

    const int T = 256;
    int gbCount = (EE / 4 + T - 1) / T;
    int gbE     = (EE + T - 1) / T;
    int gbGemm  = (NN + 63) / 64;
    int gbGat   = (NN * 32 + T - 1) / T;
    int gbAgg   = (NN * 32 + T - 1) / T;
    int gbOut   = (BT * 32 + T - 1) / T;

    // side stream + events (created fresh per call; NOT destroyed — destroying
    // a stream/event participating in an active capture would invalidate it.
    // Host-side handles only; no device memory.)
    cudaStream_t s2;
    cudaStreamCreateWithFlags(&s2, cudaStreamNonBlocking);
    cudaEvent_t evFork, evJoin;
    cudaEventCreateWithFlags(&evFork, cudaEventDisableTiming);
    cudaEventCreateWithFlags(&evJoin, cudaEventDisableTiming);

    // ---- fork: CSR build on s2 ----
    cudaEventRecord(evFork, 0);
    cudaStreamWaitEvent(s2, evFork, 0);
    cudaMemsetAsync(cnt, 0, NPAD * sizeof(int), s2);
    k_count<<<gbCount, T, 0, s2>>>((const int4*)dst);
    k_scan<<<1, 1024, 0, s2>>>();
    k_scatter<<<gbE, T, 0, s2>>>(src, dst);
    cudaEventRecord(evJoin, s2);

    // ---- main stream: fp16 prep + layer-0 GEMM (overlaps CSR build) ----
    k_gather_h<<<gbGat, T>>>((const float4*)emb, nf, (const float4*)W0, (const float4*)W1);
    k_gemm<<<gbGemm, T, GEMM_SMEM>>>(h0h, Wh0, al0, ar0, z, el, er);

    // ---- join: aggregates need the CSR ----
    cudaStreamWaitEvent(0, evJoin, 0);

    // layer 0 (residual = emb[nf[n]]; activation on; writes fp16 twin h1h)
    k_aggregate<<<gbAgg, T>>>((const uint2*)z, el, er, emb, nf, b0, h1, h1h, 1, 0);

    // layer 1 (no activation; L2-normalize fused)
    k_gemm<<<gbGemm, T, GEMM_SMEM>>>(h1h, Wh1, al1, ar1, z, el, er);
    k_aggregate<<<gbAgg, T>>>((const uint2*)z, el, er, h1, nullptr, b1, hf, nullptr, 0, 1);

    // final gather
    k_output<<<gbOut, T>>>((const float4*)hf, x, (float4*)out);
}

// round 13
// speedup vs baseline: 1.0212x; 1.0212x over previous
#include <cuda_runtime.h>
#include <cuda_fp16.h>

// ---- problem constants (hardcoded in reference module) ----
#define NN 57254
#define EE 916064
#define NPAD 57344           // 1024*56, padded counter array
#define BT 32768             // B*T
#define NCHUNK0 28672        // agg0/gemm1 pipeline split (448*64)

// ---- device scratch (static: no allocation allowed) ----
__device__ float  g_h1[NN * 128];     // layer-1 residual input (fp32)
__device__ float  g_hf[NN * 128];     // final normalized features
__device__ __half g_h0h[NN * 128];    // fp16 GEMM input, layer 0 (emb gathered)
__device__ __half g_h1h[NN * 128];    // fp16 GEMM input, layer 1
__device__ __half g_Wh0[128 * 128];
__device__ __half g_Wh1[128 * 128];
__device__ __half g_z [NN * 128];
__device__ float  g_el[NN * 8];
__device__ float  g_er[NN * 8];
__device__ int    g_rowptr[NN + 1];
__device__ int    g_cnt[NPAD];
__device__ int    g_csrc[EE];

// ---------------------------------------------------------------------------
// CSR build: count (int4), single-block 2-pass scan (also seeds g_cnt with
// the exclusive prefix so scatter needs no second memset), scatter
// ---------------------------------------------------------------------------
__global__ void k_count(const int4* __restrict__ dst4) {
    int i = blockIdx.x * blockDim.x + threadIdx.x;
    if (i < EE / 4) {
        int4 d = dst4[i];
        atomicAdd(&g_cnt[d.x], 1);
        atomicAdd(&g_cnt[d.y], 1);
        atomicAdd(&g_cnt[d.z], 1);
        atomicAdd(&g_cnt[d.w], 1);
    }
}

__global__ __launch_bounds__(1024) void k_scan() {
    __shared__ int wsum[32];
    int t = threadIdx.x;
    int lane = t & 31, wid = t >> 5;
    const int4* c4 = (const int4*)g_cnt;

    int tot = 0;
    int4 vv[14];
    #pragma unroll
    for (int j = 0; j < 14; j++) {
        vv[j] = c4[t * 14 + j];
        tot += vv[j].x + vv[j].y + vv[j].z + vv[j].w;
    }
    int s = tot;
    #pragma unroll
    for (int o = 1; o < 32; o <<= 1) {
        int u = __shfl_up_sync(0xffffffffu, s, o);
        if (lane >= o) s += u;
    }
    if (lane == 31) wsum[wid] = s;
    __syncthreads();
    if (wid == 0) {
        int wv = wsum[lane];
        #pragma unroll
        for (int o = 1; o < 32; o <<= 1) {
            int u = __shfl_up_sync(0xffffffffu, wv, o);
            if (lane >= o) wv += u;
        }
        wsum[lane] = wv;
    }
    __syncthreads();
    int run = s - tot + (wid > 0 ? wsum[wid - 1] : 0);

    #pragma unroll
    for (int j = 0; j < 14; j++) {
        int4 v = vv[j];
        int idx = t * 56 + j * 4;
        if (idx + 3 < NN) {
            int4 o;
            o.x = run;             o.y = run + v.x;
            o.z = run + v.x + v.y; o.w = run + v.x + v.y + v.z;
            *(int4*)(g_rowptr + idx) = o;
            *(int4*)(g_cnt + idx) = o;          // scatter works in-place on cnt
            run += v.x + v.y + v.z + v.w;
        } else {
            if (idx     < NN) { g_rowptr[idx]     = run; g_cnt[idx]     = run; } run += v.x;
            if (idx + 1 < NN) { g_rowptr[idx + 1] = run; g_cnt[idx + 1] = run; } run += v.y;
            if (idx + 2 < NN) { g_rowptr[idx + 2] = run; g_cnt[idx + 2] = run; } run += v.z;
            if (idx + 3 < NN) { g_rowptr[idx + 3] = run; g_cnt[idx + 3] = run; } run += v.w;
        }
    }
    if (t == 1023) g_rowptr[NN] = EE;
}

__global__ void k_scatter(const int* __restrict__ src, const int* __restrict__ dst) {
    int i = blockIdx.x * blockDim.x + threadIdx.x;
    if (i >= EE) return;
    int pos = atomicAdd(&g_cnt[dst[i]], 1);
    g_csrc[pos] = src[i];
}

// ---------------------------------------------------------------------------
// fp16 input prep: emb[nf[n]] -> half h0; first 4096 threads also convert W0/W1
// ---------------------------------------------------------------------------
__global__ void k_gather_h(const float4* __restrict__ emb,
                           const int* __restrict__ nf,
                           const float4* __restrict__ W0,
                           const float4* __restrict__ W1) {
    int i = blockIdx.x * blockDim.x + threadIdx.x;   // NN*32 float4 slots
    if (i < 4096) {                                  // 128*128 floats = 4096 float4
        float4 w0 = W0[i], w1 = W1[i];
        __half2 a0 = __floats2half2_rn(w0.x, w0.y), b0 = __floats2half2_rn(w0.z, w0.w);
        __half2 a1 = __floats2half2_rn(w1.x, w1.y), b1 = __floats2half2_rn(w1.z, w1.w);
        uint2 u0, u1;
        u0.x = *(unsigned*)&a0; u0.y = *(unsigned*)&b0;
        u1.x = *(unsigned*)&a1; u1.y = *(unsigned*)&b1;
        *(uint2*)(g_Wh0 + i * 4) = u0;
        *(uint2*)(g_Wh1 + i * 4) = u1;
    }
    if (i >= NN * 32) return;
    int n = i >> 5, l = i & 31;
    float4 v = emb[(long)nf[n] * 32 + l];
    __half2 lo = __floats2half2_rn(v.x, v.y);
    __half2 hi = __floats2half2_rn(v.z, v.w);
    uint2 u;
    u.x = *(unsigned*)&lo;
    u.y = *(unsigned*)&hi;
    *(uint2*)(g_h0h + (long)n * 128 + l * 4) = u;
}

// ---------------------------------------------------------------------------
// fp16 tensor-core GEMM with fused scores:
//   z(fp16) = h @ W;  el = z . al;  er = z . ar
// 64x128 block tile, 256 threads (8 warps 2x4), warp tile 32x32
// (m16n8k16). Full tiles staged once via cp.async; ldmatrix feeds mma.
// rowoff: row-range chunking for cross-stream pipelining.
// ---------------------------------------------------------------------------
__device__ __forceinline__ void mma16(float* c, const unsigned* a,
                                      unsigned b0, unsigned b1) {
    asm volatile(
        "mma.sync.aligned.m16n8k16.row.col.f32.f16.f16.f32 "
        "{%0,%1,%2,%3},{%4,%5,%6,%7},{%8,%9},{%0,%1,%2,%3};"
        : "+f"(c[0]), "+f"(c[1]), "+f"(c[2]), "+f"(c[3])
        : "r"(a[0]), "r"(a[1]), "r"(a[2]), "r"(a[3]), "r"(b0), "r"(b1));
}

__device__ __forceinline__ void ldmx4(unsigned* r, unsigned addr) {
    asm volatile("ldmatrix.sync.aligned.m8n8.x4.shared.b16 {%0,%1,%2,%3}, [%4];"
                 : "=r"(r[0]), "=r"(r[1]), "=r"(r[2]), "=r"(r[3]) : "r"(addr));
}

__device__ __forceinline__ void ldmx4t(unsigned* r, unsigned addr) {
    asm volatile("ldmatrix.sync.aligned.m8n8.x4.trans.shared.b16 {%0,%1,%2,%3}, [%4];"
                 : "=r"(r[0]), "=r"(r[1]), "=r"(r[2]), "=r"(r[3]) : "r"(addr));
}

__device__ __forceinline__ void cpasync16(void* smem, const void* gmem, int bytes) {
    unsigned s = (unsigned)__cvta_generic_to_shared(smem);
    asm volatile("cp.async.cg.shared.global [%0], [%1], 16, %2;"
                 :: "r"(s), "l"(gmem), "r"(bytes));
}
#define CP_COMMIT() asm volatile("cp.async.commit_group;")

#define HST 136                          // halves per smem row (272 B)
#define GEMM_SMEM ((64 * HST + 128 * HST) * 2)

__global__ __launch_bounds__(256, 3) void k_gemm(const __half* __restrict__ Ah,
                                                 const __half* __restrict__ Wh,
                                                 const float* __restrict__ al,
                                                 const float* __restrict__ ar,
                                                 __half* __restrict__ z,
                                                 float* __restrict__ el,
                                                 float* __restrict__ er,
                                                 int rowoff) {
    extern __shared__ __half smh[];
    __half* sA = smh;               // 64 x HST
    __half* sB = smh + 64 * HST;    // 128 x HST (W, k-major)

    int t = threadIdx.x;
    int rowbase = rowoff + blockIdx.x * 64;
    int warp = t >> 5, lane = t & 31;
    int qr = lane >> 2, qc = lane & 3;
    int wm = (warp >> 2) * 32;
    int wn = (warp & 3) * 32;

    // ---- stage full A (64x128) and B (128x128) tiles ----
    #pragma unroll
    for (int j = 0; j < 4; j++) {
        int idx = t + j * 256;          // 0..1023
        int row = idx >> 4, seg = idx & 15;
        int gr = rowbase + row;
        const void* ga = (gr < NN) ? (const void*)(Ah + (long)gr * 128 + seg * 8)
                                   : (const void*)Ah;
        cpasync16(sA + row * HST + seg * 8, ga, gr < NN ? 16 : 0);
    }
    #pragma unroll
    for (int j = 0; j < 8; j++) {
        int idx = t + j * 256;          // 0..2047
        int row = idx >> 4, seg = idx & 15;
        cpasync16(sB + row * HST + seg * 8, Wh + (long)row * 128 + seg * 8, 16);
    }
    CP_COMMIT();

    float c[2][4][4];
    #pragma unroll
    for (int mt = 0; mt < 2; mt++)
        #pragma unroll
        for (int nt = 0; nt < 4; nt++)
            #pragma unroll
            for (int i = 0; i < 4; i++) c[mt][nt][i] = 0.f;

    unsigned sAsh = (unsigned)__cvta_generic_to_shared(sA);
    unsigned sBsh = (unsigned)__cvta_generic_to_shared(sB);
    int l8  = lane & 7;
    int m01 = (lane >> 3) & 1;
    int hi  = lane >> 4;
    unsigned aAddr0 = sAsh + ((wm + m01 * 8 + l8) * HST + hi * 8) * 2;
    unsigned aAddr1 = aAddr0 + 16 * HST * 2;
    unsigned bAddr0 = sBsh + ((m01 * 8 + l8) * HST + wn + hi * 8) * 2;
    unsigned bAddr1 = bAddr0 + 16 * 2;

    asm volatile("cp.async.wait_group 0;");
    __syncthreads();

    #pragma unroll
    for (int ks = 0; ks < 8; ks++) {
        unsigned a0[4], a1[4], b0[4], b1[4];
        ldmx4 (a0, aAddr0 + ks * 32);
        ldmx4 (a1, aAddr1 + ks * 32);
        ldmx4t(b0, bAddr0 + ks * 16 * HST * 2);
        ldmx4t(b1, bAddr1 + ks * 16 * HST * 2);
        mma16(c[0][0], a0, b0[0], b0[1]);
        mma16(c[1][0], a1, b0[0], b0[1]);
        mma16(c[0][1], a0, b0[2], b0[3]);
        mma16(c[1][1], a1, b0[2], b0[3]);
        mma16(c[0][2], a0, b1[0], b1[1]);
        mma16(c[1][2], a1, b1[0], b1[1]);
        mma16(c[0][3], a0, b1[2], b1[3]);
        mma16(c[1][3], a1, b1[2], b1[3]);
    }

    // ---- epilogue 1: store z as fp16 ----
    #pragma unroll
    for (int mt = 0; mt < 2; mt++) {
        int r0 = rowbase + wm + mt * 16 + qr;
        int r1 = r0 + 8;
        #pragma unroll
        for (int nt = 0; nt < 4; nt++) {
            int col = wn + nt * 8 + qc * 2;
            if (r0 < NN)
                *(__half2*)(z + (long)r0 * 128 + col) = __floats2half2_rn(c[mt][nt][0], c[mt][nt][1]);
            if (r1 < NN)
                *(__half2*)(z + (long)r1 * 128 + col) = __floats2half2_rn(c[mt][nt][2], c[mt][nt][3]);
        }
    }

    // ---- epilogue 2: fused el/er scores ----
    float alv[8], arv[8];
    #pragma unroll
    for (int nt = 0; nt < 4; nt++) {
        #pragma unroll
        for (int u = 0; u < 2; u++) {
            int col = wn + nt * 8 + qc * 2 + u;
            alv[nt * 2 + u] = __ldg(al + col);
            arv[nt * 2 + u] = __ldg(ar + col);
        }
    }
    #pragma unroll
    for (int mt = 0; mt < 2; mt++) {
        #pragma unroll
        for (int rh = 0; rh < 2; rh++) {
            #pragma unroll
            for (int hl = 0; hl < 2; hl++) {
                float pl = 0.f, pr = 0.f;
                #pragma unroll
                for (int k = 0; k < 2; k++) {
                    int nt = hl * 2 + k;
                    pl += c[mt][nt][rh * 2]     * alv[nt * 2]
                        + c[mt][nt][rh * 2 + 1] * alv[nt * 2 + 1];
                    pr += c[mt][nt][rh * 2]     * arv[nt * 2]
                        + c[mt][nt][rh * 2 + 1] * arv[nt * 2 + 1];
                }
                pl += __shfl_xor_sync(0xffffffffu, pl, 1);
                pl += __shfl_xor_sync(0xffffffffu, pl, 2);
                pr += __shfl_xor_sync(0xffffffffu, pr, 1);
                pr += __shfl_xor_sync(0xffffffffu, pr, 2);
                if ((lane & 3) == 0) {
                    int row = rowbase + wm + mt * 16 + qr + rh * 8;
                    if (row < NN) {
                        int hidx = (wn >> 4) + hl;
                        el[row * 8 + hidx] = pl;
                        er[row * 8 + hidx] = pr;
                    }
                }
            }
        }
    }
}

// ---------------------------------------------------------------------------
// Per-dst edge softmax + aggregate + residual + bias (+ leaky_relu / L2 norm).
// One warp/node, 4-edge software pipeline (round-7/11 proven form).
// nodebase/nodecount: node-range chunking for cross-stream pipelining.
// ---------------------------------------------------------------------------
__global__ __launch_bounds__(256) void k_aggregate(const uint2* __restrict__ zh,
                                                   const float* __restrict__ el,
                                                   const float* __restrict__ er,
                                                   const float* __restrict__ hin,
                                                   const int* __restrict__ nfmap,
                                                   const float* __restrict__ bias,
                                                   float* __restrict__ hout,
                                                   __half* __restrict__ houth,
                                                   int activate, int normalize,
                                                   int nodebase, int nodecount) {
    int wlocal = (blockIdx.x * blockDim.x + threadIdx.x) >> 5;
    int lane = threadIdx.x & 31;
    if (wlocal >= nodecount) return;
    int warp = nodebase + wlocal;
    int hd = lane >> 2;
    float erh = er[warp * 8 + hd];
    int beg = g_rowptr[warp], end = g_rowptr[warp + 1];
    float s = 0.f;
    float4 acc = make_float4(0.f, 0.f, 0.f, 0.f);

    int e = beg;
    for (; e + 4 <= end; e += 4) {
        int s0 = g_csrc[e],     s1 = g_csrc[e + 1];
        int s2 = g_csrc[e + 2], s3 = g_csrc[e + 3];
        float x0 = el[s0 * 8 + hd], x1 = el[s1 * 8 + hd];
        float x2 = el[s2 * 8 + hd], x3 = el[s3 * 8 + hd];
        uint2 qa = zh[(long)s0 * 32 + lane], qb = zh[(long)s1 * 32 + lane];
        uint2 qc = zh[(long)s2 * 32 + lane], qd = zh[(long)s3 * 32 + lane];
        x0 += erh; x0 = x0 > 0.f ? x0 : 0.2f * x0; float a0 = __expf(x0);
        x1 += erh; x1 = x1 > 0.f ? x1 : 0.2f * x1; float a1 = __expf(x1);
        x2 += erh; x2 = x2 > 0.f ? x2 : 0.2f * x2; float a2 = __expf(x2);
        x3 += erh; x3 = x3 > 0.f ? x3 : 0.2f * x3; float a3 = __expf(x3);
        float2 p, q;
        p = __half22float2(*(__half2*)&qa.x); q = __half22float2(*(__half2*)&qa.y);
        s += a0; acc.x += a0 * p.x; acc.y += a0 * p.y; acc.z += a0 * q.x; acc.w += a0 * q.y;
        p = __half22float2(*(__half2*)&qb.x); q = __half22float2(*(__half2*)&qb.y);
        s += a1; acc.x += a1 * p.x; acc.y += a1 * p.y; acc.z += a1 * q.x; acc.w += a1 * q.y;
        p = __half22float2(*(__half2*)&qc.x); q = __half22float2(*(__half2*)&qc.y);
        s += a2; acc.x += a2 * p.x; acc.y += a2 * p.y; acc.z += a2 * q.x; acc.w += a2 * q.y;
        p = __half22float2(*(__half2*)&qd.x); q = __half22float2(*(__half2*)&qd.y);
        s += a3; acc.x += a3 * p.x; acc.y += a3 * p.y; acc.z += a3 * q.x; acc.w += a3 * q.y;
    }
    for (; e < end; e++) {
        int sr = g_csrc[e];
        float x = el[sr * 8 + hd] + erh;
        x = x > 0.f ? x : 0.2f * x;
        float a = __expf(x);
        uint2 qa = zh[(long)sr * 32 + lane];
        float2 p = __half22float2(*(__half2*)&qa.x);
        float2 q = __half22float2(*(__half2*)&qa.y);
        s += a;
        acc.x += a * p.x; acc.y += a * p.y; acc.z += a * q.x; acc.w += a * q.y;
    }
    float inv = (s > 0.f) ? (1.f / s) : 0.f;
    int hidx = nfmap ? nfmap[warp] : warp;
    float4 hv = ((const float4*)hin)[(long)hidx * 32 + lane];
    float4 bv = ((const float4*)bias)[lane];
    float4 o;
    o.x = acc.x * inv + hv.x + bv.x;
    o.y = acc.y * inv + hv.y + bv.y;
    o.z = acc.z * inv + hv.z + bv.z;
    o.w = acc.w * inv + hv.w + bv.w;
    if (activate) {
        o.x = o.x > 0.f ? o.x : 0.01f * o.x;
        o.y = o.y > 0.f ? o.y : 0.01f * o.y;
        o.z = o.z > 0.f ? o.z : 0.01f * o.z;
        o.w = o.w > 0.f ? o.w : 0.01f * o.w;
    }
    if (normalize) {
        float ss = o.x * o.x + o.y * o.y + o.z * o.z + o.w * o.w;
        #pragma unroll
        for (int off = 16; off; off >>= 1)
            ss += __shfl_xor_sync(0xffffffffu, ss, off);
        float inv2 = 1.f / fmaxf(sqrtf(ss), 1e-5f);
        o.x *= inv2; o.y *= inv2; o.z *= inv2; o.w *= inv2;
    }
    ((float4*)hout)[warp * 32 + lane] = o;
    if (houth) {
        __half2 lo = __floats2half2_rn(o.x, o.y);
        __half2 hi = __floats2half2_rn(o.z, o.w);
        uint2 u;
        u.x = *(unsigned*)&lo;
        u.y = *(unsigned*)&hi;
        *(uint2*)(houth + (long)warp * 128 + lane * 4) = u;
    }
}

// ---------------------------------------------------------------------------
// out[i] = h[x[i]]  (pure gather; normalization already fused)
// ---------------------------------------------------------------------------
__global__ void k_output(const float4* __restrict__ h,
                         const int* __restrict__ x,
                         float4* __restrict__ out) {
    int i = blockIdx.x * blockDim.x + threadIdx.x;
    if (i >= BT * 32) return;
    int t = i >> 5, l = i & 31;
    out[i] = h[(long)x[t] * 32 + l];
}

// ---------------------------------------------------------------------------
// host launch: CSR build forked onto side stream; agg0/gemm1 chunk-pipelined
// ---------------------------------------------------------------------------
extern "C" void kernel_launch(void* const* d_in, const int* in_sizes, int n_in,
                              void* d_out, int out_size) {
    const float* emb = (const float*)d_in[0];
    const float* W0  = (const float*)d_in[1];
    const float* al0 = (const float*)d_in[2];
    const float* ar0 = (const float*)d_in[3];
    const float* b0  = (const float*)d_in[4];
    const float* W1  = (const float*)d_in[5];
    const float* al1 = (const float*)d_in[6];
    const float* ar1 = (const float*)d_in[7];
    const float* b1  = (const float*)d_in[8];
    const int*   nf  = (const int*)d_in[9];
    const int*   src = (const int*)d_in[10];
    const int*   dst = (const int*)d_in[11];
    const int*   x   = (const int*)d_in[12];
    float* out = (float*)d_out;

    float *h1, *hf, *el, *er;
    __half *z, *h0h, *h1h, *Wh0, *Wh1;
    int *cnt;
    cudaGetSymbolAddress((void**)&h1,  g_h1);
    cudaGetSymbolAddress((void**)&hf,  g_hf);
    cudaGetSymbolAddress((void**)&z,   g_z);
    cudaGetSymbolAddress((void**)&h0h, g_h0h);
    cudaGetSymbolAddress((void**)&h1h, g_h1h);
    cudaGetSymbolAddress((void**)&Wh0, g_Wh0);
    cudaGetSymbolAddress((void**)&Wh1, g_Wh1);
    cudaGetSymbolAddress((void**)&el,  g_el);
    cudaGetSymbolAddress((void**)&er,  g_er);
    cudaGetSymbolAddress((void**)&cnt, g_cnt);

    cudaFuncSetAttribute(k_gemm, cudaFuncAttributeMaxDynamicSharedMemorySize, GEMM_SMEM);

    const int T = 256;
    const int N0 = NCHUNK0;            // first agg0 / gemm1 chunk (nodes/rows)
    const int N1 = NN - N0;
    int gbCount = (EE / 4 + T - 1) / T;
    int gbE     = (EE + T - 1) / T;
    int gbGemm  = (NN + 63) / 64;
    int gbGemmC0 = N0 / 64;
    int gbGemmC1 = (N1 + 63) / 64;
    int gbGat   = (NN * 32 + T - 1) / T;
    int gbAgg   = (NN * 32 + T - 1) / T;
    int gbAggC0 = (N0 * 32 + T - 1) / T;
    int gbAggC1 = (N1 * 32 + T - 1) / T;
    int gbOut   = (BT * 32 + T - 1) / T;

    // side stream + events (created fresh per call; NOT destroyed — destroying
    // a stream/event participating in an active capture would invalidate it.
    // Host-side handles only; no device memory.)
    cudaStream_t s2;
    cudaStreamCreateWithFlags(&s2, cudaStreamNonBlocking);
    cudaEvent_t evFork, evJoin, evA0, evA1, evG;
    cudaEventCreateWithFlags(&evFork, cudaEventDisableTiming);
    cudaEventCreateWithFlags(&evJoin, cudaEventDisableTiming);
    cudaEventCreateWithFlags(&evA0,   cudaEventDisableTiming);
    cudaEventCreateWithFlags(&evA1,   cudaEventDisableTiming);
    cudaEventCreateWithFlags(&evG,    cudaEventDisableTiming);

    // ---- fork: CSR build on s2 ----
    cudaEventRecord(evFork, 0);
    cudaStreamWaitEvent(s2, evFork, 0);
    cudaMemsetAsync(cnt, 0, NPAD * sizeof(int), s2);
    k_count<<<gbCount, T, 0, s2>>>((const int4*)dst);
    k_scan<<<1, 1024, 0, s2>>>();
    k_scatter<<<gbE, T, 0, s2>>>(src, dst);
    cudaEventRecord(evJoin, s2);

    // ---- main stream: fp16 prep + layer-0 GEMM (overlaps CSR build) ----
    k_gather_h<<<gbGat, T>>>((const float4*)emb, nf, (const float4*)W0, (const float4*)W1);
    k_gemm<<<gbGemm, T, GEMM_SMEM>>>(h0h, Wh0, al0, ar0, z, el, er, 0);

    // ---- join: aggregates need the CSR ----
    cudaStreamWaitEvent(0, evJoin, 0);

    // ---- layer 0 aggregate, chunked; gemm1 chunks pipeline on s2 ----
    k_aggregate<<<gbAggC0, T>>>((const uint2*)z, el, er, emb, nf, b0, h1, h1h,
                                1, 0, 0, N0);
    cudaEventRecord(evA0, 0);
    k_aggregate<<<gbAggC1, T>>>((const uint2*)z, el, er, emb, nf, b0, h1, h1h,
                                1, 0, N0, N1);
    cudaEventRecord(evA1, 0);

    cudaStreamWaitEvent(s2, evA0, 0);
    k_gemm<<<gbGemmC0, T, GEMM_SMEM, s2>>>(h1h, Wh1, al1, ar1, z, el, er, 0);
    cudaStreamWaitEvent(s2, evA1, 0);
    k_gemm<<<gbGemmC1, T, GEMM_SMEM, s2>>>(h1h, Wh1, al1, ar1, z, el, er, N0);
    cudaEventRecord(evG, s2);

    // ---- layer 1 aggregate needs all of gemm1's z/el/er ----
    cudaStreamWaitEvent(0, evG, 0);
    k_aggregate<<<gbAgg, T>>>((const uint2*)z, el, er, h1, nullptr, b1, hf, nullptr,
                              0, 1, 0, NN);

    // final gather
    k_output<<<gbOut, T>>>((const float4*)hf, x, (float4*)out);
}

// round 14
// speedup vs baseline: 1.0641x; 1.0420x over previous
#include <cuda_runtime.h>
#include <cuda_fp16.h>

// ---- problem constants (hardcoded in reference module) ----
#define NN 57254
#define EE 916064
#define NPAD 57344           // 1024*56, padded counter array
#define BT 32768             // B*T

// ---- device scratch (static: no allocation allowed) ----
__device__ float  g_h1[NN * 128];     // layer-1 residual input (fp32)
__device__ float  g_hf[NN * 128];     // final normalized features
__device__ __half g_h0h[NN * 128];    // fp16 GEMM input, layer 0 (emb gathered)
__device__ __half g_h1h[NN * 128];    // fp16 GEMM input, layer 1
__device__ __half g_Wh0[128 * 128];
__device__ __half g_Wh1[128 * 128];
__device__ __half g_z [NN * 128];
__device__ float  g_el[NN * 8];
__device__ float  g_er[NN * 8];
__device__ int    g_rowptr[NN + 1];
__device__ int    g_cnt[NPAD];
__device__ int    g_csrc[EE];
__device__ int    g_mark[NN];         // 1 if node appears in x (agg1 needed)

// ---------------------------------------------------------------------------
// CSR build: count (int4), single-block 2-pass scan (also seeds g_cnt with
// the exclusive prefix so scatter needs no second memset), scatter
// ---------------------------------------------------------------------------
__global__ void k_count(const int4* __restrict__ dst4) {
    int i = blockIdx.x * blockDim.x + threadIdx.x;
    if (i < EE / 4) {
        int4 d = dst4[i];
        atomicAdd(&g_cnt[d.x], 1);
        atomicAdd(&g_cnt[d.y], 1);
        atomicAdd(&g_cnt[d.z], 1);
        atomicAdd(&g_cnt[d.w], 1);
    }
}

__global__ __launch_bounds__(1024) void k_scan() {
    __shared__ int wsum[32];
    int t = threadIdx.x;
    int lane = t & 31, wid = t >> 5;
    const int4* c4 = (const int4*)g_cnt;

    int tot = 0;
    int4 vv[14];
    #pragma unroll
    for (int j = 0; j < 14; j++) {
        vv[j] = c4[t * 14 + j];
        tot += vv[j].x + vv[j].y + vv[j].z + vv[j].w;
    }
    int s = tot;
    #pragma unroll
    for (int o = 1; o < 32; o <<= 1) {
        int u = __shfl_up_sync(0xffffffffu, s, o);
        if (lane >= o) s += u;
    }
    if (lane == 31) wsum[wid] = s;
    __syncthreads();
    if (wid == 0) {
        int wv = wsum[lane];
        #pragma unroll
        for (int o = 1; o < 32; o <<= 1) {
            int u = __shfl_up_sync(0xffffffffu, wv, o);
            if (lane >= o) wv += u;
        }
        wsum[lane] = wv;
    }
    __syncthreads();
    int run = s - tot + (wid > 0 ? wsum[wid - 1] : 0);

    #pragma unroll
    for (int j = 0; j < 14; j++) {
        int4 v = vv[j];
        int idx = t * 56 + j * 4;
        if (idx + 3 < NN) {
            int4 o;
            o.x = run;             o.y = run + v.x;
            o.z = run + v.x + v.y; o.w = run + v.x + v.y + v.z;
            *(int4*)(g_rowptr + idx) = o;
            *(int4*)(g_cnt + idx) = o;          // scatter works in-place on cnt
            run += v.x + v.y + v.z + v.w;
        } else {
            if (idx     < NN) { g_rowptr[idx]     = run; g_cnt[idx]     = run; } run += v.x;
            if (idx + 1 < NN) { g_rowptr[idx + 1] = run; g_cnt[idx + 1] = run; } run += v.y;
            if (idx + 2 < NN) { g_rowptr[idx + 2] = run; g_cnt[idx + 2] = run; } run += v.z;
            if (idx + 3 < NN) { g_rowptr[idx + 3] = run; g_cnt[idx + 3] = run; } run += v.w;
        }
    }
    if (t == 1023) g_rowptr[NN] = EE;
}

__global__ void k_scatter(const int* __restrict__ src, const int* __restrict__ dst) {
    int i = blockIdx.x * blockDim.x + threadIdx.x;
    if (i >= EE) return;
    int pos = atomicAdd(&g_cnt[dst[i]], 1);
    g_csrc[pos] = src[i];
}

// ---------------------------------------------------------------------------
// mark nodes referenced by the output index tensor x
// ---------------------------------------------------------------------------
__global__ void k_mark(const int* __restrict__ x) {
    int i = blockIdx.x * blockDim.x + threadIdx.x;
    if (i < BT) g_mark[x[i]] = 1;
}

// ---------------------------------------------------------------------------
// fp16 input prep: emb[nf[n]] -> half h0; first 4096 threads also convert W0/W1
// ---------------------------------------------------------------------------
__global__ void k_gather_h(const float4* __restrict__ emb,
                           const int* __restrict__ nf,
                           const float4* __restrict__ W0,
                           const float4* __restrict__ W1) {
    int i = blockIdx.x * blockDim.x + threadIdx.x;   // NN*32 float4 slots
    if (i < 4096) {                                  // 128*128 floats = 4096 float4
        float4 w0 = W0[i], w1 = W1[i];
        __half2 a0 = __floats2half2_rn(w0.x, w0.y), b0 = __floats2half2_rn(w0.z, w0.w);
        __half2 a1 = __floats2half2_rn(w1.x, w1.y), b1 = __floats2half2_rn(w1.z, w1.w);
        uint2 u0, u1;
        u0.x = *(unsigned*)&a0; u0.y = *(unsigned*)&b0;
        u1.x = *(unsigned*)&a1; u1.y = *(unsigned*)&b1;
        *(uint2*)(g_Wh0 + i * 4) = u0;
        *(uint2*)(g_Wh1 + i * 4) = u1;
    }
    if (i >= NN * 32) return;
    int n = i >> 5, l = i & 31;
    float4 v = emb[(long)nf[n] * 32 + l];
    __half2 lo = __floats2half2_rn(v.x, v.y);
    __half2 hi = __floats2half2_rn(v.z, v.w);
    uint2 u;
    u.x = *(unsigned*)&lo;
    u.y = *(unsigned*)&hi;
    *(uint2*)(g_h0h + (long)n * 128 + l * 4) = u;
}

// ---------------------------------------------------------------------------
// fp16 tensor-core GEMM with fused scores:
//   z(fp16) = h @ W;  el = z . al;  er = z . ar
// 64x128 block tile, 256 threads (8 warps 2x4), warp tile 32x32
// (m16n8k16). Full tiles staged once via cp.async; ldmatrix feeds mma.
// ---------------------------------------------------------------------------
__device__ __forceinline__ void mma16(float* c, const unsigned* a,
                                      unsigned b0, unsigned b1) {
    asm volatile(
        "mma.sync.aligned.m16n8k16.row.col.f32.f16.f16.f32 "
        "{%0,%1,%2,%3},{%4,%5,%6,%7},{%8,%9},{%0,%1,%2,%3};"
        : "+f"(c[0]), "+f"(c[1]), "+f"(c[2]), "+f"(c[3])
        : "r"(a[0]), "r"(a[1]), "r"(a[2]), "r"(a[3]), "r"(b0), "r"(b1));
}

__device__ __forceinline__ void ldmx4(unsigned* r, unsigned addr) {
    asm volatile("ldmatrix.sync.aligned.m8n8.x4.shared.b16 {%0,%1,%2,%3}, [%4];"
                 : "=r"(r[0]), "=r"(r[1]), "=r"(r[2]), "=r"(r[3]) : "r"(addr));
}

__device__ __forceinline__ void ldmx4t(unsigned* r, unsigned addr) {
    asm volatile("ldmatrix.sync.aligned.m8n8.x4.trans.shared.b16 {%0,%1,%2,%3}, [%4];"
                 : "=r"(r[0]), "=r"(r[1]), "=r"(r[2]), "=r"(r[3]) : "r"(addr));
}

__device__ __forceinline__ void cpasync16(void* smem, const void* gmem, int bytes) {
    unsigned s = (unsigned)__cvta_generic_to_shared(smem);
    asm volatile("cp.async.cg.shared.global [%0], [%1], 16, %2;"
                 :: "r"(s), "l"(gmem), "r"(bytes));
}
#define CP_COMMIT() asm volatile("cp.async.commit_group;")

#define HST 136                          // halves per smem row (272 B)
#define GEMM_SMEM ((64 * HST + 128 * HST) * 2)

__global__ __launch_bounds__(256, 3) void k_gemm(const __half* __restrict__ Ah,
                                                 const __half* __restrict__ Wh,
                                                 const float* __restrict__ al,
                                                 const float* __restrict__ ar,
                                                 __half* __restrict__ z,
                                                 float* __restrict__ el,
                                                 float* __restrict__ er) {
    extern __shared__ __half smh[];
    __half* sA = smh;               // 64 x HST
    __half* sB = smh + 64 * HST;    // 128 x HST (W, k-major)

    int t = threadIdx.x;
    int rowbase = blockIdx.x * 64;
    int warp = t >> 5, lane = t & 31;
    int qr = lane >> 2, qc = lane & 3;
    int wm = (warp >> 2) * 32;
    int wn = (warp & 3) * 32;

    // ---- stage full A (64x128) and B (128x128) tiles ----
    #pragma unroll
    for (int j = 0; j < 4; j++) {
        int idx = t + j * 256;          // 0..1023
        int row = idx >> 4, seg = idx & 15;
        int gr = rowbase + row;
        const void* ga = (gr < NN) ? (const void*)(Ah + (long)gr * 128 + seg * 8)
                                   : (const void*)Ah;
        cpasync16(sA + row * HST + seg * 8, ga, gr < NN ? 16 : 0);
    }
    #pragma unroll
    for (int j = 0; j < 8; j++) {
        int idx = t + j * 256;          // 0..2047
        int row = idx >> 4, seg = idx & 15;
        cpasync16(sB + row * HST + seg * 8, Wh + (long)row * 128 + seg * 8, 16);
    }
    CP_COMMIT();

    float c[2][4][4];
    #pragma unroll
    for (int mt = 0; mt < 2; mt++)
        #pragma unroll
        for (int nt = 0; nt < 4; nt++)
            #pragma unroll
            for (int i = 0; i < 4; i++) c[mt][nt][i] = 0.f;

    unsigned sAsh = (unsigned)__cvta_generic_to_shared(sA);
    unsigned sBsh = (unsigned)__cvta_generic_to_shared(sB);
    int l8  = lane & 7;
    int m01 = (lane >> 3) & 1;
    int hi  = lane >> 4;
    unsigned aAddr0 = sAsh + ((wm + m01 * 8 + l8) * HST + hi * 8) * 2;
    unsigned aAddr1 = aAddr0 + 16 * HST * 2;
    unsigned bAddr0 = sBsh + ((m01 * 8 + l8) * HST + wn + hi * 8) * 2;
    unsigned bAddr1 = bAddr0 + 16 * 2;

    asm volatile("cp.async.wait_group 0;");
    __syncthreads();

    #pragma unroll
    for (int ks = 0; ks < 8; ks++) {
        unsigned a0[4], a1[4], b0[4], b1[4];
        ldmx4 (a0, aAddr0 + ks * 32);
        ldmx4 (a1, aAddr1 + ks * 32);
        ldmx4t(b0, bAddr0 + ks * 16 * HST * 2);
        ldmx4t(b1, bAddr1 + ks * 16 * HST * 2);
        mma16(c[0][0], a0, b0[0], b0[1]);
        mma16(c[1][0], a1, b0[0], b0[1]);
        mma16(c[0][1], a0, b0[2], b0[3]);
        mma16(c[1][1], a1, b0[2], b0[3]);
        mma16(c[0][2], a0, b1[0], b1[1]);
        mma16(c[1][2], a1, b1[0], b1[1]);
        mma16(c[0][3], a0, b1[2], b1[3]);
        mma16(c[1][3], a1, b1[2], b1[3]);
    }

    // ---- epilogue 1: store z as fp16 ----
    #pragma unroll
    for (int mt = 0; mt < 2; mt++) {
        int r0 = rowbase + wm + mt * 16 + qr;
        int r1 = r0 + 8;
        #pragma unroll
        for (int nt = 0; nt < 4; nt++) {
            int col = wn + nt * 8 + qc * 2;
            if (r0 < NN)
                *(__half2*)(z + (long)r0 * 128 + col) = __floats2half2_rn(c[mt][nt][0], c[mt][nt][1]);
            if (r1 < NN)
                *(__half2*)(z + (long)r1 * 128 + col) = __floats2half2_rn(c[mt][nt][2], c[mt][nt][3]);
        }
    }

    // ---- epilogue 2: fused el/er scores ----
    float alv[8], arv[8];
    #pragma unroll
    for (int nt = 0; nt < 4; nt++) {
        #pragma unroll
        for (int u = 0; u < 2; u++) {
            int col = wn + nt * 8 + qc * 2 + u;
            alv[nt * 2 + u] = __ldg(al + col);
            arv[nt * 2 + u] = __ldg(ar + col);
        }
    }
    #pragma unroll
    for (int mt = 0; mt < 2; mt++) {
        #pragma unroll
        for (int rh = 0; rh < 2; rh++) {
            #pragma unroll
            for (int hl = 0; hl < 2; hl++) {
                float pl = 0.f, pr = 0.f;
                #pragma unroll
                for (int k = 0; k < 2; k++) {
                    int nt = hl * 2 + k;
                    pl += c[mt][nt][rh * 2]     * alv[nt * 2]
                        + c[mt][nt][rh * 2 + 1] * alv[nt * 2 + 1];
                    pr += c[mt][nt][rh * 2]     * arv[nt * 2]
                        + c[mt][nt][rh * 2 + 1] * arv[nt * 2 + 1];
                }
                pl += __shfl_xor_sync(0xffffffffu, pl, 1);
                pl += __shfl_xor_sync(0xffffffffu, pl, 2);
                pr += __shfl_xor_sync(0xffffffffu, pr, 1);
                pr += __shfl_xor_sync(0xffffffffu, pr, 2);
                if ((lane & 3) == 0) {
                    int row = rowbase + wm + mt * 16 + qr + rh * 8;
                    if (row < NN) {
                        int hidx = (wn >> 4) + hl;
                        el[row * 8 + hidx] = pl;
                        er[row * 8 + hidx] = pr;
                    }
                }
            }
        }
    }
}

// ---------------------------------------------------------------------------
// Per-dst edge softmax + aggregate + residual + bias (+ leaky_relu / L2 norm).
// One warp/node, 4-edge software pipeline (round-7/11 proven form).
// mark != null: skip nodes not referenced by the output (layer 1 only).
// ---------------------------------------------------------------------------
__global__ __launch_bounds__(256) void k_aggregate(const uint2* __restrict__ zh,
                                                   const float* __restrict__ el,
                                                   const float* __restrict__ er,
                                                   const float* __restrict__ hin,
                                                   const int* __restrict__ nfmap,
                                                   const float* __restrict__ bias,
                                                   float* __restrict__ hout,
                                                   __half* __restrict__ houth,
                                                   const int* __restrict__ mark,
                                                   int activate, int normalize) {
    int warp = (blockIdx.x * blockDim.x + threadIdx.x) >> 5;
    int lane = threadIdx.x & 31;
    if (warp >= NN) return;
    if (mark && !__ldg(mark + warp)) return;
    int hd = lane >> 2;
    float erh = er[warp * 8 + hd];
    int beg = g_rowptr[warp], end = g_rowptr[warp + 1];
    float s = 0.f;
    float4 acc = make_float4(0.f, 0.f, 0.f, 0.f);

    int e = beg;
    for (; e + 4 <= end; e += 4) {
        int s0 = g_csrc[e],     s1 = g_csrc[e + 1];
        int s2 = g_csrc[e + 2], s3 = g_csrc[e + 3];
        float x0 = el[s0 * 8 + hd], x1 = el[s1 * 8 + hd];
        float x2 = el[s2 * 8 + hd], x3 = el[s3 * 8 + hd];
        uint2 qa = zh[(long)s0 * 32 + lane], qb = zh[(long)s1 * 32 + lane];
        uint2 qc = zh[(long)s2 * 32 + lane], qd = zh[(long)s3 * 32 + lane];
        x0 += erh; x0 = x0 > 0.f ? x0 : 0.2f * x0; float a0 = __expf(x0);
        x1 += erh; x1 = x1 > 0.f ? x1 : 0.2f * x1; float a1 = __expf(x1);
        x2 += erh; x2 = x2 > 0.f ? x2 : 0.2f * x2; float a2 = __expf(x2);
        x3 += erh; x3 = x3 > 0.f ? x3 : 0.2f * x3; float a3 = __expf(x3);
        float2 p, q;
        p = __half22float2(*(__half2*)&qa.x); q = __half22float2(*(__half2*)&qa.y);
        s += a0; acc.x += a0 * p.x; acc.y += a0 * p.y; acc.z += a0 * q.x; acc.w += a0 * q.y;
        p = __half22float2(*(__half2*)&qb.x); q = __half22float2(*(__half2*)&qb.y);
        s += a1; acc.x += a1 * p.x; acc.y += a1 * p.y; acc.z += a1 * q.x; acc.w += a1 * q.y;
        p = __half22float2(*(__half2*)&qc.x); q = __half22float2(*(__half2*)&qc.y);
        s += a2; acc.x += a2 * p.x; acc.y += a2 * p.y; acc.z += a2 * q.x; acc.w += a2 * q.y;
        p = __half22float2(*(__half2*)&qd.x); q = __half22float2(*(__half2*)&qd.y);
        s += a3; acc.x += a3 * p.x; acc.y += a3 * p.y; acc.z += a3 * q.x; acc.w += a3 * q.y;
    }
    for (; e < end; e++) {
        int sr = g_csrc[e];
        float x = el[sr * 8 + hd] + erh;
        x = x > 0.f ? x : 0.2f * x;
        float a = __expf(x);
        uint2 qa = zh[(long)sr * 32 + lane];
        float2 p = __half22float2(*(__half2*)&qa.x);
        float2 q = __half22float2(*(__half2*)&qa.y);
        s += a;
        acc.x += a * p.x; acc.y += a * p.y; acc.z += a * q.x; acc.w += a * q.y;
    }
    float inv = (s > 0.f) ? (1.f / s) : 0.f;
    int hidx = nfmap ? nfmap[warp] : warp;
    float4 hv = ((const float4*)hin)[(long)hidx * 32 + lane];
    float4 bv = ((const float4*)bias)[lane];
    float4 o;
    o.x = acc.x * inv + hv.x + bv.x;
    o.y = acc.y * inv + hv.y + bv.y;
    o.z = acc.z * inv + hv.z + bv.z;
    o.w = acc.w * inv + hv.w + bv.w;
    if (activate) {
        o.x = o.x > 0.f ? o.x : 0.01f * o.x;
        o.y = o.y > 0.f ? o.y : 0.01f * o.y;
        o.z = o.z > 0.f ? o.z : 0.01f * o.z;
        o.w = o.w > 0.f ? o.w : 0.01f * o.w;
    }
    if (normalize) {
        float ss = o.x * o.x + o.y * o.y + o.z * o.z + o.w * o.w;
        #pragma unroll
        for (int off = 16; off; off >>= 1)
            ss += __shfl_xor_sync(0xffffffffu, ss, off);
        float inv2 = 1.f / fmaxf(sqrtf(ss), 1e-5f);
        o.x *= inv2; o.y *= inv2; o.z *= inv2; o.w *= inv2;
    }
    ((float4*)hout)[warp * 32 + lane] = o;
    if (houth) {
        __half2 lo = __floats2half2_rn(o.x, o.y);
        __half2 hi = __floats2half2_rn(o.z, o.w);
        uint2 u;
        u.x = *(unsigned*)&lo;
        u.y = *(unsigned*)&hi;
        *(uint2*)(houth + (long)warp * 128 + lane * 4) = u;
    }
}

// ---------------------------------------------------------------------------
// out[i] = h[x[i]]  (pure gather; normalization already fused)
// ---------------------------------------------------------------------------
__global__ void k_output(const float4* __restrict__ h,
                         const int* __restrict__ x,
                         float4* __restrict__ out) {
    int i = blockIdx.x * blockDim.x + threadIdx.x;
    if (i >= BT * 32) return;
    int t = i >> 5, l = i & 31;
    out[i] = h[(long)x[t] * 32 + l];
}

// ---------------------------------------------------------------------------
// host launch: CSR build + output-mark forked onto a side stream,
// overlapping fp16 prep + GEMM-0 (round-11 structure)
// ---------------------------------------------------------------------------
extern "C" void kernel_launch(void* const* d_in, const int* in_sizes, int n_in,
                              void* d_out, int out_size) {
    const float* emb = (const float*)d_in[0];
    const float* W0  = (const float*)d_in[1];
    const float* al0 = (const float*)d_in[2];
    const float* ar0 = (const float*)d_in[3];
    const float* b0  = (const float*)d_in[4];
    const float* W1  = (const float*)d_in[5];
    const float* al1 = (const float*)d_in[6];
    const float* ar1 = (const float*)d_in[7];
    const float* b1  = (const float*)d_in[8];
    const int*   nf  = (const int*)d_in[9];
    const int*   src = (const int*)d_in[10];
    const int*   dst = (const int*)d_in[11];
    const int*   x   = (const int*)d_in[12];
    float* out = (float*)d_out;

    float *h1, *hf, *el, *er;
    __half *z, *h0h, *h1h, *Wh0, *Wh1;
    int *cnt, *mark;
    cudaGetSymbolAddress((void**)&h1,  g_h1);
    cudaGetSymbolAddress((void**)&hf,  g_hf);
    cudaGetSymbolAddress((void**)&z,   g_z);
    cudaGetSymbolAddress((void**)&h0h, g_h0h);
    cudaGetSymbolAddress((void**)&h1h, g_h1h);
    cudaGetSymbolAddress((void**)&Wh0, g_Wh0);
    cudaGetSymbolAddress((void**)&Wh1, g_Wh1);
    cudaGetSymbolAddress((void**)&el,  g_el);
    cudaGetSymbolAddress((void**)&er,  g_er);
    cudaGetSymbolAddress((void**)&cnt, g_cnt);
    cudaGetSymbolAddress((void**)&mark, g_mark);

    cudaFuncSetAttribute(k_gemm, cudaFuncAttributeMaxDynamicSharedMemorySize, GEMM_SMEM);

    const int T = 256;
    int gbCount = (EE / 4 + T - 1) / T;
    int gbE     = (EE + T - 1) / T;
    int gbGemm  = (NN + 63) / 64;
    int gbGat   = (NN * 32 + T - 1) / T;
    int gbAgg   = (NN * 32 + T - 1) / T;
    int gbMark  = (BT + T - 1) / T;
    int gbOut   = (BT * 32 + T - 1) / T;

    // side stream + events (created fresh per call; NOT destroyed — destroying
    // a stream/event participating in an active capture would invalidate it.
    // Host-side handles only; no device memory.)
    cudaStream_t s2;
    cudaStreamCreateWithFlags(&s2, cudaStreamNonBlocking);
    cudaEvent_t evFork, evJoin;
    cudaEventCreateWithFlags(&evFork, cudaEventDisableTiming);
    cudaEventCreateWithFlags(&evJoin, cudaEventDisableTiming);

    // ---- fork: CSR build + output mark on s2 ----
    cudaEventRecord(evFork, 0);
    cudaStreamWaitEvent(s2, evFork, 0);
    cudaMemsetAsync(cnt, 0, NPAD * sizeof(int), s2);
    cudaMemsetAsync(mark, 0, NN * sizeof(int), s2);
    k_count<<<gbCount, T, 0, s2>>>((const int4*)dst);
    k_mark<<<gbMark, T, 0, s2>>>(x);
    k_scan<<<1, 1024, 0, s2>>>();
    k_scatter<<<gbE, T, 0, s2>>>(src, dst);
    cudaEventRecord(evJoin, s2);

    // ---- main stream: fp16 prep + layer-0 GEMM (overlaps CSR build) ----
    k_gather_h<<<gbGat, T>>>((const float4*)emb, nf, (const float4*)W0, (const float4*)W1);
    k_gemm<<<gbGemm, T, GEMM_SMEM>>>(h0h, Wh0, al0, ar0, z, el, er);

    // ---- join: aggregates need the CSR ----
    cudaStreamWaitEvent(0, evJoin, 0);

    // layer 0 (residual = emb[nf[n]]; activation on; writes fp16 twin h1h)
    k_aggregate<<<gbAgg, T>>>((const uint2*)z, el, er, emb, nf, b0, h1, h1h,
                              nullptr, 1, 0);

    // layer 1 (no activation; L2-normalize fused; only output-referenced nodes)
    k_gemm<<<gbGemm, T, GEMM_SMEM>>>(h1h, Wh1, al1, ar1, z, el, er);
    k_aggregate<<<gbAgg, T>>>((const uint2*)z, el, er, h1, nullptr, b1, hf,
                              nullptr, mark, 0, 1);

    // final gather
    k_output<<<gbOut, T>>>((const float4*)hf, x, (float4*)out);
}

// round 15
// speedup vs baseline: 1.0677x; 1.0034x over previous
#include <cuda_runtime.h>
#include <cuda_fp16.h>

// ---- problem constants (hardcoded in reference module) ----
#define NN 57254
#define EE 916064
#define NPAD 57344           // 1024*56, padded counter array
#define BT 32768             // B*T

// ---- device scratch (static: no allocation allowed) ----
__device__ float  g_h1[NN * 128];     // layer-1 residual input (fp32)
__device__ float  g_hf[NN * 128];     // final normalized features
__device__ __half g_h0h[NN * 128];    // fp16 GEMM input, layer 0 (emb gathered)
__device__ __half g_h1h[NN * 128];    // fp16 GEMM input, layer 1
__device__ __half g_Wh0[128 * 128];
__device__ __half g_Wh1[128 * 128];
__device__ __half g_z [NN * 128];
__device__ float  g_el[NN * 8];
__device__ float  g_er[NN * 8];
__device__ int    g_rowptr[NN + 1];
__device__ int    g_cnt[NPAD];
__device__ int    g_csrc[EE];
__device__ int    g_mark[NN];         // 1 if node appears in x (agg1 needed)

// ---------------------------------------------------------------------------
// CSR build: count (int4), single-block 2-pass scan (also seeds g_cnt with
// the exclusive prefix so scatter needs no second memset), scatter (4 edges
// per thread for atomic MLP)
// ---------------------------------------------------------------------------
__global__ void k_count(const int4* __restrict__ dst4) {
    int i = blockIdx.x * blockDim.x + threadIdx.x;
    if (i < EE / 4) {
        int4 d = dst4[i];
        atomicAdd(&g_cnt[d.x], 1);
        atomicAdd(&g_cnt[d.y], 1);
        atomicAdd(&g_cnt[d.z], 1);
        atomicAdd(&g_cnt[d.w], 1);
    }
}

__global__ __launch_bounds__(1024) void k_scan() {
    __shared__ int wsum[32];
    int t = threadIdx.x;
    int lane = t & 31, wid = t >> 5;
    const int4* c4 = (const int4*)g_cnt;

    int tot = 0;
    int4 vv[14];
    #pragma unroll
    for (int j = 0; j < 14; j++) {
        vv[j] = c4[t * 14 + j];
        tot += vv[j].x + vv[j].y + vv[j].z + vv[j].w;
    }
    int s = tot;
    #pragma unroll
    for (int o = 1; o < 32; o <<= 1) {
        int u = __shfl_up_sync(0xffffffffu, s, o);
        if (lane >= o) s += u;
    }
    if (lane == 31) wsum[wid] = s;
    __syncthreads();
    if (wid == 0) {
        int wv = wsum[lane];
        #pragma unroll
        for (int o = 1; o < 32; o <<= 1) {
            int u = __shfl_up_sync(0xffffffffu, wv, o);
            if (lane >= o) wv += u;
        }
        wsum[lane] = wv;
    }
    __syncthreads();
    int run = s - tot + (wid > 0 ? wsum[wid - 1] : 0);

    #pragma unroll
    for (int j = 0; j < 14; j++) {
        int4 v = vv[j];
        int idx = t * 56 + j * 4;
        if (idx + 3 < NN) {
            int4 o;
            o.x = run;             o.y = run + v.x;
            o.z = run + v.x + v.y; o.w = run + v.x + v.y + v.z;
            *(int4*)(g_rowptr + idx) = o;
            *(int4*)(g_cnt + idx) = o;          // scatter works in-place on cnt
            run += v.x + v.y + v.z + v.w;
        } else {
            if (idx     < NN) { g_rowptr[idx]     = run; g_cnt[idx]     = run; } run += v.x;
            if (idx + 1 < NN) { g_rowptr[idx + 1] = run; g_cnt[idx + 1] = run; } run += v.y;
            if (idx + 2 < NN) { g_rowptr[idx + 2] = run; g_cnt[idx + 2] = run; } run += v.z;
            if (idx + 3 < NN) { g_rowptr[idx + 3] = run; g_cnt[idx + 3] = run; } run += v.w;
        }
    }
    if (t == 1023) g_rowptr[NN] = EE;
}

__global__ void k_scatter(const int4* __restrict__ src4, const int4* __restrict__ dst4) {
    int i = blockIdx.x * blockDim.x + threadIdx.x;
    if (i >= EE / 4) return;
    int4 d = dst4[i];
    int4 sv = src4[i];
    // 4 independent atomics in flight (latency overlapped), then scattered stores
    int p0 = atomicAdd(&g_cnt[d.x], 1);
    int p1 = atomicAdd(&g_cnt[d.y], 1);
    int p2 = atomicAdd(&g_cnt[d.z], 1);
    int p3 = atomicAdd(&g_cnt[d.w], 1);
    g_csrc[p0] = sv.x;
    g_csrc[p1] = sv.y;
    g_csrc[p2] = sv.z;
    g_csrc[p3] = sv.w;
}

// ---------------------------------------------------------------------------
// mark nodes referenced by the output index tensor x
// ---------------------------------------------------------------------------
__global__ void k_mark(const int* __restrict__ x) {
    int i = blockIdx.x * blockDim.x + threadIdx.x;
    if (i < BT) g_mark[x[i]] = 1;
}

// ---------------------------------------------------------------------------
// fp16 input prep: emb[nf[n]] -> half h0; first 4096 threads also convert W0/W1
// ---------------------------------------------------------------------------
__global__ void k_gather_h(const float4* __restrict__ emb,
                           const int* __restrict__ nf,
                           const float4* __restrict__ W0,
                           const float4* __restrict__ W1) {
    int i = blockIdx.x * blockDim.x + threadIdx.x;   // NN*32 float4 slots
    if (i < 4096) {                                  // 128*128 floats = 4096 float4
        float4 w0 = W0[i], w1 = W1[i];
        __half2 a0 = __floats2half2_rn(w0.x, w0.y), b0 = __floats2half2_rn(w0.z, w0.w);
        __half2 a1 = __floats2half2_rn(w1.x, w1.y), b1 = __floats2half2_rn(w1.z, w1.w);
        uint2 u0, u1;
        u0.x = *(unsigned*)&a0; u0.y = *(unsigned*)&b0;
        u1.x = *(unsigned*)&a1; u1.y = *(unsigned*)&b1;
        *(uint2*)(g_Wh0 + i * 4) = u0;
        *(uint2*)(g_Wh1 + i * 4) = u1;
    }
    if (i >= NN * 32) return;
    int n = i >> 5, l = i & 31;
    float4 v = emb[(long)nf[n] * 32 + l];
    __half2 lo = __floats2half2_rn(v.x, v.y);
    __half2 hi = __floats2half2_rn(v.z, v.w);
    uint2 u;
    u.x = *(unsigned*)&lo;
    u.y = *(unsigned*)&hi;
    *(uint2*)(g_h0h + (long)n * 128 + l * 4) = u;
}

// ---------------------------------------------------------------------------
// fp16 tensor-core GEMM with fused scores:
//   z(fp16) = h @ W;  el = z . al;  er = z . ar
// 64x128 block tile, 256 threads (8 warps 2x4), warp tile 32x32
// (m16n8k16). Full tiles staged once via cp.async; ldmatrix feeds mma.
// ---------------------------------------------------------------------------
__device__ __forceinline__ void mma16(float* c, const unsigned* a,
                                      unsigned b0, unsigned b1) {
    asm volatile(
        "mma.sync.aligned.m16n8k16.row.col.f32.f16.f16.f32 "
        "{%0,%1,%2,%3},{%4,%5,%6,%7},{%8,%9},{%0,%1,%2,%3};"
        : "+f"(c[0]), "+f"(c[1]), "+f"(c[2]), "+f"(c[3])
        : "r"(a[0]), "r"(a[1]), "r"(a[2]), "r"(a[3]), "r"(b0), "r"(b1));
}

__device__ __forceinline__ void ldmx4(unsigned* r, unsigned addr) {
    asm volatile("ldmatrix.sync.aligned.m8n8.x4.shared.b16 {%0,%1,%2,%3}, [%4];"
                 : "=r"(r[0]), "=r"(r[1]), "=r"(r[2]), "=r"(r[3]) : "r"(addr));
}

__device__ __forceinline__ void ldmx4t(unsigned* r, unsigned addr) {
    asm volatile("ldmatrix.sync.aligned.m8n8.x4.trans.shared.b16 {%0,%1,%2,%3}, [%4];"
                 : "=r"(r[0]), "=r"(r[1]), "=r"(r[2]), "=r"(r[3]) : "r"(addr));
}

__device__ __forceinline__ void cpasync16(void* smem, const void* gmem, int bytes) {
    unsigned s = (unsigned)__cvta_generic_to_shared(smem);
    asm volatile("cp.async.cg.shared.global [%0], [%1], 16, %2;"
                 :: "r"(s), "l"(gmem), "r"(bytes));
}
#define CP_COMMIT() asm volatile("cp.async.commit_group;")

#define HST 136                          // halves per smem row (272 B)
#define GEMM_SMEM ((64 * HST + 128 * HST) * 2)

__global__ __launch_bounds__(256, 3) void k_gemm(const __half* __restrict__ Ah,
                                                 const __half* __restrict__ Wh,
                                                 const float* __restrict__ al,
                                                 const float* __restrict__ ar,
                                                 __half* __restrict__ z,
                                                 float* __restrict__ el,
                                                 float* __restrict__ er) {
    extern __shared__ __half smh[];
    __half* sA = smh;               // 64 x HST
    __half* sB = smh + 64 * HST;    // 128 x HST (W, k-major)

    int t = threadIdx.x;
    int rowbase = blockIdx.x * 64;
    int warp = t >> 5, lane = t & 31;
    int qr = lane >> 2, qc = lane & 3;
    int wm = (warp >> 2) * 32;
    int wn = (warp & 3) * 32;

    // ---- stage full A (64x128) and B (128x128) tiles ----
    #pragma unroll
    for (int j = 0; j < 4; j++) {
        int idx = t + j * 256;          // 0..1023
        int row = idx >> 4, seg = idx & 15;
        int gr = rowbase + row;
        const void* ga = (gr < NN) ? (const void*)(Ah + (long)gr * 128 + seg * 8)
                                   : (const void*)Ah;
        cpasync16(sA + row * HST + seg * 8, ga, gr < NN ? 16 : 0);
    }
    #pragma unroll
    for (int j = 0; j < 8; j++) {
        int idx = t + j * 256;          // 0..2047
        int row = idx >> 4, seg = idx & 15;
        cpasync16(sB + row * HST + seg * 8, Wh + (long)row * 128 + seg * 8, 16);
    }
    CP_COMMIT();

    float c[2][4][4];
    #pragma unroll
    for (int mt = 0; mt < 2; mt++)
        #pragma unroll
        for (int nt = 0; nt < 4; nt++)
            #pragma unroll
            for (int i = 0; i < 4; i++) c[mt][nt][i] = 0.f;

    unsigned sAsh = (unsigned)__cvta_generic_to_shared(sA);
    unsigned sBsh = (unsigned)__cvta_generic_to_shared(sB);
    int l8  = lane & 7;
    int m01 = (lane >> 3) & 1;
    int hi  = lane >> 4;
    unsigned aAddr0 = sAsh + ((wm + m01 * 8 + l8) * HST + hi * 8) * 2;
    unsigned aAddr1 = aAddr0 + 16 * HST * 2;
    unsigned bAddr0 = sBsh + ((m01 * 8 + l8) * HST + wn + hi * 8) * 2;
    unsigned bAddr1 = bAddr0 + 16 * 2;

    asm volatile("cp.async.wait_group 0;");
    __syncthreads();

    #pragma unroll
    for (int ks = 0; ks < 8; ks++) {
        unsigned a0[4], a1[4], b0[4], b1[4];
        ldmx4 (a0, aAddr0 + ks * 32);
        ldmx4 (a1, aAddr1 + ks * 32);
        ldmx4t(b0, bAddr0 + ks * 16 * HST * 2);
        ldmx4t(b1, bAddr1 + ks * 16 * HST * 2);
        mma16(c[0][0], a0, b0[0], b0[1]);
        mma16(c[1][0], a1, b0[0], b0[1]);
        mma16(c[0][1], a0, b0[2], b0[3]);
        mma16(c[1][1], a1, b0[2], b0[3]);
        mma16(c[0][2], a0, b1[0], b1[1]);
        mma16(c[1][2], a1, b1[0], b1[1]);
        mma16(c[0][3], a0, b1[2], b1[3]);
        mma16(c[1][3], a1, b1[2], b1[3]);
    }

    // ---- epilogue 1: store z as fp16 ----
    #pragma unroll
    for (int mt = 0; mt < 2; mt++) {
        int r0 = rowbase + wm + mt * 16 + qr;
        int r1 = r0 + 8;
        #pragma unroll
        for (int nt = 0; nt < 4; nt++) {
            int col = wn + nt * 8 + qc * 2;
            if (r0 < NN)
                *(__half2*)(z + (long)r0 * 128 + col) = __floats2half2_rn(c[mt][nt][0], c[mt][nt][1]);
            if (r1 < NN)
                *(__half2*)(z + (long)r1 * 128 + col) = __floats2half2_rn(c[mt][nt][2], c[mt][nt][3]);
        }
    }

    // ---- epilogue 2: fused el/er scores ----
    float alv[8], arv[8];
    #pragma unroll
    for (int nt = 0; nt < 4; nt++) {
        #pragma unroll
        for (int u = 0; u < 2; u++) {
            int col = wn + nt * 8 + qc * 2 + u;
            alv[nt * 2 + u] = __ldg(al + col);
            arv[nt * 2 + u] = __ldg(ar + col);
        }
    }
    #pragma unroll
    for (int mt = 0; mt < 2; mt++) {
        #pragma unroll
        for (int rh = 0; rh < 2; rh++) {
            #pragma unroll
            for (int hl = 0; hl < 2; hl++) {
                float pl = 0.f, pr = 0.f;
                #pragma unroll
                for (int k = 0; k < 2; k++) {
                    int nt = hl * 2 + k;
                    pl += c[mt][nt][rh * 2]     * alv[nt * 2]
                        + c[mt][nt][rh * 2 + 1] * alv[nt * 2 + 1];
                    pr += c[mt][nt][rh * 2]     * arv[nt * 2]
                        + c[mt][nt][rh * 2 + 1] * arv[nt * 2 + 1];
                }
                pl += __shfl_xor_sync(0xffffffffu, pl, 1);
                pl += __shfl_xor_sync(0xffffffffu, pl, 2);
                pr += __shfl_xor_sync(0xffffffffu, pr, 1);
                pr += __shfl_xor_sync(0xffffffffu, pr, 2);
                if ((lane & 3) == 0) {
                    int row = rowbase + wm + mt * 16 + qr + rh * 8;
                    if (row < NN) {
                        int hidx = (wn >> 4) + hl;
                        el[row * 8 + hidx] = pl;
                        er[row * 8 + hidx] = pr;
                    }
                }
            }
        }
    }
}

// ---------------------------------------------------------------------------
// Per-dst edge softmax + aggregate + residual + bias (+ leaky_relu / L2 norm).
// One warp/node, 4-edge software pipeline (round-7/11 proven form).
// mark != null: skip nodes not referenced by the output (layer 1 only).
// ---------------------------------------------------------------------------
__global__ __launch_bounds__(256) void k_aggregate(const uint2* __restrict__ zh,
                                                   const float* __restrict__ el,
                                                   const float* __restrict__ er,
                                                   const float* __restrict__ hin,
                                                   const int* __restrict__ nfmap,
                                                   const float* __restrict__ bias,
                                                   float* __restrict__ hout,
                                                   __half* __restrict__ houth,
                                                   const int* __restrict__ mark,
                                                   int activate, int normalize) {
    int warp = (blockIdx.x * blockDim.x + threadIdx.x) >> 5;
    int lane = threadIdx.x & 31;
    if (warp >= NN) return;
    if (mark && !__ldg(mark + warp)) return;
    int hd = lane >> 2;
    float erh = er[warp * 8 + hd];
    int beg = g_rowptr[warp], end = g_rowptr[warp + 1];
    float s = 0.f;
    float4 acc = make_float4(0.f, 0.f, 0.f, 0.f);

    int e = beg;
    for (; e + 4 <= end; e += 4) {
        int s0 = g_csrc[e],     s1 = g_csrc[e + 1];
        int s2 = g_csrc[e + 2], s3 = g_csrc[e + 3];
        float x0 = el[s0 * 8 + hd], x1 = el[s1 * 8 + hd];
        float x2 = el[s2 * 8 + hd], x3 = el[s3 * 8 + hd];
        uint2 qa = zh[(long)s0 * 32 + lane], qb = zh[(long)s1 * 32 + lane];
        uint2 qc = zh[(long)s2 * 32 + lane], qd = zh[(long)s3 * 32 + lane];
        x0 += erh; x0 = x0 > 0.f ? x0 : 0.2f * x0; float a0 = __expf(x0);
        x1 += erh; x1 = x1 > 0.f ? x1 : 0.2f * x1; float a1 = __expf(x1);
        x2 += erh; x2 = x2 > 0.f ? x2 : 0.2f * x2; float a2 = __expf(x2);
        x3 += erh; x3 = x3 > 0.f ? x3 : 0.2f * x3; float a3 = __expf(x3);
        float2 p, q;
        p = __half22float2(*(__half2*)&qa.x); q = __half22float2(*(__half2*)&qa.y);
        s += a0; acc.x += a0 * p.x; acc.y += a0 * p.y; acc.z += a0 * q.x; acc.w += a0 * q.y;
        p = __half22float2(*(__half2*)&qb.x); q = __half22float2(*(__half2*)&qb.y);
        s += a1; acc.x += a1 * p.x; acc.y += a1 * p.y; acc.z += a1 * q.x; acc.w += a1 * q.y;
        p = __half22float2(*(__half2*)&qc.x); q = __half22float2(*(__half2*)&qc.y);
        s += a2; acc.x += a2 * p.x; acc.y += a2 * p.y; acc.z += a2 * q.x; acc.w += a2 * q.y;
        p = __half22float2(*(__half2*)&qd.x); q = __half22float2(*(__half2*)&qd.y);
        s += a3; acc.x += a3 * p.x; acc.y += a3 * p.y; acc.z += a3 * q.x; acc.w += a3 * q.y;
    }
    for (; e < end; e++) {
        int sr = g_csrc[e];
        float x = el[sr * 8 + hd] + erh;
        x = x > 0.f ? x : 0.2f * x;
        float a = __expf(x);
        uint2 qa = zh[(long)sr * 32 + lane];
        float2 p = __half22float2(*(__half2*)&qa.x);
        float2 q = __half22float2(*(__half2*)&qa.y);
        s += a;
        acc.x += a * p.x; acc.y += a * p.y; acc.z += a * q.x; acc.w += a * q.y;
    }
    float inv = (s > 0.f) ? (1.f / s) : 0.f;
    int hidx = nfmap ? nfmap[warp] : warp;
    float4 hv = ((const float4*)hin)[(long)hidx * 32 + lane];
    float4 bv = ((const float4*)bias)[lane];
    float4 o;
    o.x = acc.x * inv + hv.x + bv.x;
    o.y = acc.y * inv + hv.y + bv.y;
    o.z = acc.z * inv + hv.z + bv.z;
    o.w = acc.w * inv + hv.w + bv.w;
    if (activate) {
        o.x = o.x > 0.f ? o.x : 0.01f * o.x;
        o.y = o.y > 0.f ? o.y : 0.01f * o.y;
        o.z = o.z > 0.f ? o.z : 0.01f * o.z;
        o.w = o.w > 0.f ? o.w : 0.01f * o.w;
    }
    if (normalize) {
        float ss = o.x * o.x + o.y * o.y + o.z * o.z + o.w * o.w;
        #pragma unroll
        for (int off = 16; off; off >>= 1)
            ss += __shfl_xor_sync(0xffffffffu, ss, off);
        float inv2 = 1.f / fmaxf(sqrtf(ss), 1e-5f);
        o.x *= inv2; o.y *= inv2; o.z *= inv2; o.w *= inv2;
    }
    ((float4*)hout)[warp * 32 + lane] = o;
    if (houth) {
        __half2 lo = __floats2half2_rn(o.x, o.y);
        __half2 hi = __floats2half2_rn(o.z, o.w);
        uint2 u;
        u.x = *(unsigned*)&lo;
        u.y = *(unsigned*)&hi;
        *(uint2*)(houth + (long)warp * 128 + lane * 4) = u;
    }
}

// ---------------------------------------------------------------------------
// out[i] = h[x[i]]  (pure gather; normalization already fused)
// ---------------------------------------------------------------------------
__global__ void k_output(const float4* __restrict__ h,
                         const int* __restrict__ x,
                         float4* __restrict__ out) {
    int i = blockIdx.x * blockDim.x + threadIdx.x;
    if (i >= BT * 32) return;
    int t = i >> 5, l = i & 31;
    out[i] = h[(long)x[t] * 32 + l];
}

// ---------------------------------------------------------------------------
// host launch: CSR build + output-mark forked onto a side stream,
// overlapping fp16 prep + GEMM-0 (round-11 structure)
// ---------------------------------------------------------------------------
extern "C" void kernel_launch(void* const* d_in, const int* in_sizes, int n_in,
                              void* d_out, int out_size) {
    const float* emb = (const float*)d_in[0];
    const float* W0  = (const float*)d_in[1];
    const float* al0 = (const float*)d_in[2];
    const float* ar0 = (const float*)d_in[3];
    const float* b0  = (const float*)d_in[4];
    const float* W1  = (const float*)d_in[5];
    const float* al1 = (const float*)d_in[6];
    const float* ar1 = (const float*)d_in[7];
    const float* b1  = (const float*)d_in[8];
    const int*   nf  = (const int*)d_in[9];
    const int*   src = (const int*)d_in[10];
    const int*   dst = (const int*)d_in[11];
    const int*   x   = (const int*)d_in[12];
    float* out = (float*)d_out;

    float *h1, *hf, *el, *er;
    __half *z, *h0h, *h1h, *Wh0, *Wh1;
    int *cnt, *mark;
    cudaGetSymbolAddress((void**)&h1,  g_h1);
    cudaGetSymbolAddress((void**)&hf,  g_hf);
    cudaGetSymbolAddress((void**)&z,   g_z);
    cudaGetSymbolAddress((void**)&h0h, g_h0h);
    cudaGetSymbolAddress((void**)&h1h, g_h1h);
    cudaGetSymbolAddress((void**)&Wh0, g_Wh0);
    cudaGetSymbolAddress((void**)&Wh1, g_Wh1);
    cudaGetSymbolAddress((void**)&el,  g_el);
    cudaGetSymbolAddress((void**)&er,  g_er);
    cudaGetSymbolAddress((void**)&cnt, g_cnt);
    cudaGetSymbolAddress((void**)&mark, g_mark);

    cudaFuncSetAttribute(k_gemm, cudaFuncAttributeMaxDynamicSharedMemorySize, GEMM_SMEM);

    const int T = 256;
    int gbCount = (EE / 4 + T - 1) / T;
    int gbGemm  = (NN + 63) / 64;
    int gbGat   = (NN * 32 + T - 1) / T;
    int gbAgg   = (NN * 32 + T - 1) / T;
    int gbMark  = (BT + T - 1) / T;
    int gbOut   = (BT * 32 + T - 1) / T;

    // side stream + events (created fresh per call; NOT destroyed — destroying
    // a stream/event participating in an active capture would invalidate it.
    // Host-side handles only; no device memory.)
    cudaStream_t s2;
    cudaStreamCreateWithFlags(&s2, cudaStreamNonBlocking);
    cudaEvent_t evFork, evJoin;
    cudaEventCreateWithFlags(&evFork, cudaEventDisableTiming);
    cudaEventCreateWithFlags(&evJoin, cudaEventDisableTiming);

    // ---- fork: CSR build + output mark on s2 ----
    cudaEventRecord(evFork, 0);
    cudaStreamWaitEvent(s2, evFork, 0);
    cudaMemsetAsync(cnt, 0, NPAD * sizeof(int), s2);
    cudaMemsetAsync(mark, 0, NN * sizeof(int), s2);
    k_count<<<gbCount, T, 0, s2>>>((const int4*)dst);
    k_mark<<<gbMark, T, 0, s2>>>(x);
    k_scan<<<1, 1024, 0, s2>>>();
    k_scatter<<<gbCount, T, 0, s2>>>((const int4*)src, (const int4*)dst);
    cudaEventRecord(evJoin, s2);

    // ---- main stream: fp16 prep + layer-0 GEMM (overlaps CSR build) ----
    k_gather_h<<<gbGat, T>>>((const float4*)emb, nf, (const float4*)W0, (const float4*)W1);
    k_gemm<<<gbGemm, T, GEMM_SMEM>>>(h0h, Wh0, al0, ar0, z, el, er);

    // ---- join: aggregates need the CSR ----
    cudaStreamWaitEvent(0, evJoin, 0);

    // layer 0 (residual = emb[nf[n]]; activation on; writes fp16 twin h1h)
    k_aggregate<<<gbAgg, T>>>((const uint2*)z, el, er, emb, nf, b0, h1, h1h,
                              nullptr, 1, 0);

    // layer 1 (no activation; L2-normalize fused; only output-referenced nodes)
    k_gemm<<<gbGemm, T, GEMM_SMEM>>>(h1h, Wh1, al1, ar1, z, el, er);
    k_aggregate<<<gbAgg, T>>>((const uint2*)z, el, er, h1, nullptr, b1, hf,
                              nullptr, mark, 0, 1);

    // final gather
    k_output<<<gbOut, T>>>((const float4*)hf, x, (float4*)out);
}